// round 1
// baseline (speedup 1.0000x reference)
#include <cuda_runtime.h>
#include <cstdint>

// ---------------- problem constants ----------------
#define TSEQ   4096
#define EMB    300
#define HID    500
#define HP     512            // padded hidden (zero pad 500..511)
#define GATES  2000           // 4*HID, torch gate order i,f,g,o
#define NCLS   90

// ---------------- persistent-kernel config ----------------
#define NB0    42             // layer-0 CTAs, 12 units each (42*12=504 >= 500)
#define U0     12
#define NB1    96             // layer-1 CTAs, 6 units each (96*6=576 >= 500)
#define U1     6
#define NBLK   (NB0 + NB1)    // 138 <= 148 SMs -> all co-resident
#define THREADS 256           // 8 warps
#define RPW    6              // (half-)rows per warp: 48 rows / 8 warps

// ---------------- device scratch (static allocation only) ----------------
__device__ float g_xp0[(size_t)TSEQ * GATES];       // precomputed x-projection, layer 0 (32.8 MB)
__device__ float g_h1[(TSEQ + 1) * HP];             // layer-0 hidden sequence (row 0 = zeros)
__device__ float g_h2[(TSEQ + 1) * HP];             // layer-1 hidden sequence (row 0 = zeros)
__device__ int   g_r1[TSEQ + 1];                    // #layer0 CTAs done writing g_h1 row t
__device__ int   g_r2[TSEQ + 1];                    // #layer1 CTAs done writing g_h2 row t
__device__ float g_Wt[EMB * GATES];                 // W_ih0 transposed: [e][g]

// ---------------- init: reset sync counters (every replay) ----------------
__global__ void k_init() {
    int i = blockIdx.x * 256 + threadIdx.x;
    if (i <= TSEQ) {
        g_r1[i] = (i == 0) ? NB0 : 0;
        g_r2[i] = (i == 0) ? NB1 : 0;
    }
}

// ---------------- transpose W_ih0 [2000,300] -> [300,2000] ----------------
__global__ void k_transpose(const float* __restrict__ W) {
    int idx = blockIdx.x * 256 + threadIdx.x;
    if (idx < EMB * GATES) {
        int e = idx / GATES;
        int g = idx % GATES;
        g_Wt[idx] = W[g * EMB + e];
    }
}

// ---------------- x-projection GEMM: xp0[t][g] = emb[seq[t]] . W_ih0[g] + b ----------------
// grid (16, 256), block 128. Each block: 128 gates x 16 timesteps.
__global__ void k_xproj(const int* __restrict__ seq,
                        const float* __restrict__ emb,
                        const float* __restrict__ bih0,
                        const float* __restrict__ bhh0) {
    __shared__ __align__(16) float embs[16][304];   // 300 padded to 304 (16B rows)
    int g  = blockIdx.x * 128 + threadIdx.x;
    int t0 = blockIdx.y * 16;

    for (int idx = threadIdx.x; idx < 16 * 304; idx += 128) {
        int tt = idx / 304, e = idx % 304;
        float v = 0.f;
        if (e < EMB) v = emb[(size_t)seq[t0 + tt] * EMB + e];
        embs[tt][e] = v;
    }
    __syncthreads();

    float acc[16];
    float b = (g < GATES) ? (bih0[g] + bhh0[g]) : 0.f;
#pragma unroll
    for (int tt = 0; tt < 16; tt++) acc[tt] = b;

    for (int e4 = 0; e4 < 75; e4++) {               // 75*4 = 300
        float w0 = 0.f, w1 = 0.f, w2 = 0.f, w3 = 0.f;
        if (g < GATES) {
            w0 = g_Wt[(e4 * 4 + 0) * GATES + g];
            w1 = g_Wt[(e4 * 4 + 1) * GATES + g];
            w2 = g_Wt[(e4 * 4 + 2) * GATES + g];
            w3 = g_Wt[(e4 * 4 + 3) * GATES + g];
        }
#pragma unroll
        for (int tt = 0; tt < 16; tt++) {
            float4 ev = *reinterpret_cast<const float4*>(&embs[tt][e4 * 4]);
            acc[tt] = fmaf(ev.x, w0, fmaf(ev.y, w1, fmaf(ev.z, w2, fmaf(ev.w, w3, acc[tt]))));
        }
    }
    if (g < GATES) {
#pragma unroll
        for (int tt = 0; tt < 16; tt++)
            g_xp0[(size_t)(t0 + tt) * GATES + g] = acc[tt];
    }
}

__device__ __forceinline__ float sigf(float x) { return 1.f / (1.f + __expf(-x)); }

// ---------------- persistent 2-layer LSTM recurrence ----------------
// CTAs [0, NB0): layer 0. CTAs [NB0, NBLK): layer 1.
// Weights register-resident (96 regs/lane). One counter atomic per CTA per step.
__global__ __launch_bounds__(THREADS, 1)
void k_lstm(const float* __restrict__ Whh0,
            const float* __restrict__ Wih1,
            const float* __restrict__ Whh1,
            const float* __restrict__ bih1,
            const float* __restrict__ bhh1) {
    int b   = blockIdx.x;
    int tid = threadIdx.x;
    int w = tid >> 5, l = tid & 31;

    __shared__ float xA[HP];
    __shared__ float xB[HP];
    __shared__ float sums[48];
    __shared__ float xps[48];     // layer0: per-step xp values; layer1: biases (static)
    __shared__ float c_s[U0];     // cell state for owned units (max 12)

    float wreg[RPW][16];

    if (b < NB0) {
        // ======================= LAYER 0 =======================
        int ub = b * U0;
#pragma unroll
        for (int j = 0; j < RPW; j++) {
            int r = w * RPW + j;          // 0..47
            int q = r / U0, u = r % U0;
            int ug = ub + u;
            int grow = q * HID + ug;
#pragma unroll
            for (int k = 0; k < 16; k++) {
                int idx = l + 32 * k;
                wreg[j][k] = (ug < HID && idx < HID) ? Whh0[grow * HID + idx] : 0.f;
            }
        }
        if (tid < U0) c_s[tid] = 0.f;
        __syncthreads();

        for (int t = 0; t < TSEQ; t++) {
            if (tid == 0) {
                while (((volatile int*)g_r1)[t] < NB0) __nanosleep(40);
            }
            __syncthreads();
            // stage h1(t-1) into smem + prefetch this step's xp slice
            xA[tid]       = __ldcg(&g_h1[t * HP + tid]);
            xA[tid + 256] = __ldcg(&g_h1[t * HP + tid + 256]);
            if (tid < 48) {
                int q = tid / U0, u = tid % U0;
                int ug = ub + u;
                xps[tid] = (ug < HID) ? __ldcg(&g_xp0[(size_t)t * GATES + q * HID + ug]) : 0.f;
            }
            __syncthreads();

            float x[16];
#pragma unroll
            for (int k = 0; k < 16; k++) x[k] = xA[l + 32 * k];
#pragma unroll
            for (int j = 0; j < RPW; j++) {
                float acc = 0.f;
#pragma unroll
                for (int k = 0; k < 16; k++) acc = fmaf(wreg[j][k], x[k], acc);
#pragma unroll
                for (int off = 16; off; off >>= 1)
                    acc += __shfl_xor_sync(0xffffffffu, acc, off);
                if (l == 0) sums[w * RPW + j] = acc;
            }
            __syncthreads();

            if (tid < U0) {
                int u = tid, ug = ub + u;
                float pi = sums[0 * U0 + u] + xps[0 * U0 + u];
                float pf = sums[1 * U0 + u] + xps[1 * U0 + u];
                float pg = sums[2 * U0 + u] + xps[2 * U0 + u];
                float po = sums[3 * U0 + u] + xps[3 * U0 + u];
                float ig = sigf(pi), fg = sigf(pf), og = sigf(po);
                float gg = tanhf(pg);
                float c  = fg * c_s[u] + ig * gg;
                c_s[u] = c;
                float h = og * tanhf(c);
                if (ug < HID) __stcg(&g_h1[(t + 1) * HP + ug], h);
                __threadfence();
            }
            __syncthreads();
            if (tid == 0) {
                __threadfence();
                atomicAdd(&g_r1[t + 1], 1);
            }
        }
    } else {
        // ======================= LAYER 1 =======================
        int bb = b - NB0;
        int ub = bb * U1;
#pragma unroll
        for (int j = 0; j < RPW; j++) {
            int hr = w * RPW + j;          // 0..47 half-rows; [0,24)=W_ih1, [24,48)=W_hh1
            int rl = hr % 24;
            int q = rl / U1, u = rl % U1;
            int ug = ub + u;
            int grow = q * HID + ug;
            const float* W = (hr >= 24) ? Whh1 : Wih1;
#pragma unroll
            for (int k = 0; k < 16; k++) {
                int idx = l + 32 * k;
                wreg[j][k] = (ug < HID && idx < HID) ? W[grow * HID + idx] : 0.f;
            }
        }
        if (tid < 24) {
            int q = tid / U1, u = tid % U1;
            int ug = ub + u;
            int grow = q * HID + ug;
            xps[tid] = (ug < HID) ? (bih1[grow] + bhh1[grow]) : 0.f;
        }
        if (tid < U1) c_s[tid] = 0.f;
        __syncthreads();

        for (int t = 0; t < TSEQ; t++) {
            // need h1(t) (= g_h1 row t+1) and h2(t-1) (= g_h2 row t)
            if (tid == 0)  { while (((volatile int*)g_r1)[t + 1] < NB0) __nanosleep(40); }
            if (tid == 32) { while (((volatile int*)g_r2)[t]     < NB1) __nanosleep(40); }
            __syncthreads();
            xA[tid]       = __ldcg(&g_h1[(t + 1) * HP + tid]);
            xA[tid + 256] = __ldcg(&g_h1[(t + 1) * HP + tid + 256]);
            xB[tid]       = __ldcg(&g_h2[t * HP + tid]);
            xB[tid + 256] = __ldcg(&g_h2[t * HP + tid + 256]);
            __syncthreads();

            const float* xs = (w >= 4) ? xB : xA;   // warps 0-3: W_ih1 half, 4-7: W_hh1 half
            float x[16];
#pragma unroll
            for (int k = 0; k < 16; k++) x[k] = xs[l + 32 * k];
#pragma unroll
            for (int j = 0; j < RPW; j++) {
                float acc = 0.f;
#pragma unroll
                for (int k = 0; k < 16; k++) acc = fmaf(wreg[j][k], x[k], acc);
#pragma unroll
                for (int off = 16; off; off >>= 1)
                    acc += __shfl_xor_sync(0xffffffffu, acc, off);
                if (l == 0) sums[w * RPW + j] = acc;
            }
            __syncthreads();

            if (tid < U1) {
                int u = tid, ug = ub + u;
                float pi = sums[0 * U1 + u] + sums[24 + 0 * U1 + u] + xps[0 * U1 + u];
                float pf = sums[1 * U1 + u] + sums[24 + 1 * U1 + u] + xps[1 * U1 + u];
                float pg = sums[2 * U1 + u] + sums[24 + 2 * U1 + u] + xps[2 * U1 + u];
                float po = sums[3 * U1 + u] + sums[24 + 3 * U1 + u] + xps[3 * U1 + u];
                float ig = sigf(pi), fg = sigf(pf), og = sigf(po);
                float gg = tanhf(pg);
                float c  = fg * c_s[u] + ig * gg;
                c_s[u] = c;
                float h = og * tanhf(c);
                if (ug < HID) __stcg(&g_h2[(t + 1) * HP + ug], h);
                __threadfence();
            }
            __syncthreads();
            if (tid == 0) {
                __threadfence();
                atomicAdd(&g_r2[t + 1], 1);
            }
        }
    }
}

// ---------------- final FC: out = h2[last] @ fc_W^T + fc_b ----------------
__global__ void k_fc(const float* __restrict__ fcW,
                     const float* __restrict__ fcb,
                     float* __restrict__ out) {
    int b = blockIdx.x;        // class
    int l = threadIdx.x;       // lane
    float acc = 0.f;
    for (int k = l; k < HID; k += 32)
        acc += fcW[b * HID + k] * g_h2[TSEQ * HP + k];
#pragma unroll
    for (int off = 16; off; off >>= 1)
        acc += __shfl_xor_sync(0xffffffffu, acc, off);
    if (l == 0) out[b] = acc + fcb[b];
}

// ---------------- launch ----------------
extern "C" void kernel_launch(void* const* d_in, const int* in_sizes, int n_in,
                              void* d_out, int out_size) {
    const int*   seq  = (const int*)  d_in[0];
    const float* emb  = (const float*)d_in[1];
    const float* Wih0 = (const float*)d_in[2];
    const float* Whh0 = (const float*)d_in[3];
    const float* bih0 = (const float*)d_in[4];
    const float* bhh0 = (const float*)d_in[5];
    const float* Wih1 = (const float*)d_in[6];
    const float* Whh1 = (const float*)d_in[7];
    const float* bih1 = (const float*)d_in[8];
    const float* bhh1 = (const float*)d_in[9];
    const float* fcW  = (const float*)d_in[10];
    const float* fcb  = (const float*)d_in[11];

    k_init<<<(TSEQ + 1 + 255) / 256, 256>>>();
    k_transpose<<<(EMB * GATES + 255) / 256, 256>>>(Wih0);
    dim3 gx(16, 256);
    k_xproj<<<gx, 128>>>(seq, emb, bih0, bhh0);
    k_lstm<<<NBLK, THREADS>>>(Whh0, Wih1, Whh1, bih1, bhh1);
    k_fc<<<NCLS, 32>>>(fcW, fcb, (float*)d_out);
}